// round 5
// baseline (speedup 1.0000x reference)
#include <cuda_runtime.h>
#include <cuda_bf16.h>
#include <cstdint>
#include <cstddef>

// ---------------------------------------------------------------------------
// HouseholderFlow: z' = chain of 8 Householder reflections, v-chain via GEMMs.
//   v0 = h_last @ W0^T + b0 ; z = HF(v0, z)
//   v_{j+1} = v_j @ Ws[j]^T + bs[j] ; z = HF(v_{j+1}, z)
// GEMMs run on tensor cores in bf16 with a 3-term hi/lo split (~fp32 accuracy):
//   x*y ~= hi_x*hi_y + hi_x*lo_y + lo_x*hi_y   (lo*lo ~ 2^-18 rel, dropped)
// ---------------------------------------------------------------------------

#define B_DIM 8192
#define L_DIM 2048
#define NFLOW 8

#define BM 128
#define BN 128
#define BK 32
#define SST 40   // smem leading dim in bf16 elems (BK + 8 pad) -> 80B rows, LDSM conflict-free

// ---- device scratch (allocation-free rule: static __device__ arrays) ----
__device__ __nv_bfloat16 g_Whi[(size_t)NFLOW * L_DIM * L_DIM];
__device__ __nv_bfloat16 g_Wlo[(size_t)NFLOW * L_DIM * L_DIM];
__device__ __nv_bfloat16 g_Ahi[2ull * B_DIM * L_DIM];   // ping/pong v hi planes
__device__ __nv_bfloat16 g_Alo[2ull * B_DIM * L_DIM];   // ping/pong v lo planes
__device__ float         g_z[(size_t)B_DIM * L_DIM];

// ---------------------------------------------------------------------------
__device__ __forceinline__ void split2(float x, __nv_bfloat16& h, __nv_bfloat16& l) {
    h = __float2bfloat16_rn(x);
    l = __float2bfloat16_rn(x - __bfloat162float(h));
}

// fp32 -> (hi, lo) bf16 planes, vectorized
__global__ void convert_split_kernel(const float4* __restrict__ src,
                                     __nv_bfloat16* __restrict__ hi,
                                     __nv_bfloat16* __restrict__ lo,
                                     int n4) {
    int i = blockIdx.x * blockDim.x + threadIdx.x;
    if (i >= n4) return;
    float4 x = src[i];
    __nv_bfloat16 h0, h1, h2, h3, l0, l1, l2, l3;
    split2(x.x, h0, l0); split2(x.y, h1, l1);
    split2(x.z, h2, l2); split2(x.w, h3, l3);
    __nv_bfloat162* H = reinterpret_cast<__nv_bfloat162*>(hi) + 2 * (size_t)i;
    __nv_bfloat162* L = reinterpret_cast<__nv_bfloat162*>(lo) + 2 * (size_t)i;
    H[0] = __halves2bfloat162(h0, h1);
    H[1] = __halves2bfloat162(h2, h3);
    L[0] = __halves2bfloat162(l0, l1);
    L[1] = __halves2bfloat162(l2, l3);
}

// ---------------------------------------------------------------------------
// C[m,n] = sum_k A[m,k] * W[n,k] + bias[n]   (NT, both operands k-contiguous)
// K-space = 3 regions of 2048: (Ahi,Whi), (Ahi,Wlo), (Alo,Whi).
// Output written as (hi, lo) bf16 split for the next GEMM / reflection.
// ---------------------------------------------------------------------------
__global__ __launch_bounds__(256, 2)
void gemm_split_kernel(const __nv_bfloat16* __restrict__ Ahi,
                       const __nv_bfloat16* __restrict__ Alo,
                       const __nv_bfloat16* __restrict__ Whi,
                       const __nv_bfloat16* __restrict__ Wlo,
                       const float* __restrict__ bias,
                       __nv_bfloat16* __restrict__ Ohi,
                       __nv_bfloat16* __restrict__ Olo) {
    __shared__ __nv_bfloat16 As[2][BM * SST];
    __shared__ __nv_bfloat16 Bs[2][BN * SST];

    const int tid  = threadIdx.x;
    const int lane = tid & 31;
    const int warp = tid >> 5;
    const int wr   = warp >> 1;   // warp row 0..3 (32 rows each)
    const int wc   = warp & 1;    // warp col 0..1 (64 cols each)
    const int bm   = blockIdx.y * BM;
    const int bn   = blockIdx.x * BN;

    const int lrow = tid >> 2;          // 0..63  (loader row)
    const int lvec = (tid & 3) << 3;    // 0,8,16,24 (bf16 offset, 16B vectors)

    float acc[2][8][4];
#pragma unroll
    for (int mi = 0; mi < 2; mi++)
#pragma unroll
        for (int ni = 0; ni < 8; ni++)
#pragma unroll
            for (int e = 0; e < 4; e++) acc[mi][ni][e] = 0.f;

    const int TILES = 3 * (L_DIM / BK);   // 192

    auto issue = [&](int t, int buf) {
        const int r  = t >> 6;             // region 0..2
        const int kk = (t & 63) << 5;      // k offset within region
        const __nv_bfloat16* Ap = ((r < 2) ? Ahi : Alo);
        const __nv_bfloat16* Bp = ((r == 1) ? Wlo : Whi);
#pragma unroll
        for (int h = 0; h < 2; h++) {
            const int row = lrow + h * 64;
            uint32_t da = (uint32_t)__cvta_generic_to_shared(&As[buf][row * SST + lvec]);
            const void* ga = Ap + (size_t)(bm + row) * L_DIM + kk + lvec;
            asm volatile("cp.async.cg.shared.global [%0], [%1], 16;\n"
                         :: "r"(da), "l"(ga) : "memory");
            uint32_t db = (uint32_t)__cvta_generic_to_shared(&Bs[buf][row * SST + lvec]);
            const void* gb = Bp + (size_t)(bn + row) * L_DIM + kk + lvec;
            asm volatile("cp.async.cg.shared.global [%0], [%1], 16;\n"
                         :: "r"(db), "l"(gb) : "memory");
        }
        asm volatile("cp.async.commit_group;\n" ::: "memory");
    };

    issue(0, 0);

    for (int t = 0; t < TILES; t++) {
        const int buf = t & 1;
        if (t + 1 < TILES) {
            issue(t + 1, buf ^ 1);
            asm volatile("cp.async.wait_group 1;\n" ::: "memory");
        } else {
            asm volatile("cp.async.wait_group 0;\n" ::: "memory");
        }
        __syncthreads();

#pragma unroll
        for (int ks = 0; ks < 2; ks++) {
            const int kk = ks * 16;
            uint32_t a[2][4];
#pragma unroll
            for (int mi = 0; mi < 2; mi++) {
                const int row = wr * 32 + mi * 16 + (lane & 15);
                uint32_t addr = (uint32_t)__cvta_generic_to_shared(
                    &As[buf][row * SST + kk + ((lane >> 4) << 3)]);
                asm volatile(
                    "ldmatrix.sync.aligned.m8n8.x4.shared.b16 {%0,%1,%2,%3}, [%4];"
                    : "=r"(a[mi][0]), "=r"(a[mi][1]), "=r"(a[mi][2]), "=r"(a[mi][3])
                    : "r"(addr));
            }
            uint32_t b[8][2];
#pragma unroll
            for (int nt = 0; nt < 4; nt++) {
                const int nrow = wc * 64 + nt * 16 + ((lane >> 4) << 3) + (lane & 7);
                uint32_t addr = (uint32_t)__cvta_generic_to_shared(
                    &Bs[buf][nrow * SST + kk + (((lane >> 3) & 1) << 3)]);
                asm volatile(
                    "ldmatrix.sync.aligned.m8n8.x4.shared.b16 {%0,%1,%2,%3}, [%4];"
                    : "=r"(b[2 * nt][0]), "=r"(b[2 * nt][1]),
                      "=r"(b[2 * nt + 1][0]), "=r"(b[2 * nt + 1][1])
                    : "r"(addr));
            }
#pragma unroll
            for (int mi = 0; mi < 2; mi++)
#pragma unroll
                for (int ni = 0; ni < 8; ni++)
                    asm volatile(
                        "mma.sync.aligned.m16n8k16.row.col.f32.bf16.bf16.f32 "
                        "{%0,%1,%2,%3}, {%4,%5,%6,%7}, {%8,%9}, {%0,%1,%2,%3};"
                        : "+f"(acc[mi][ni][0]), "+f"(acc[mi][ni][1]),
                          "+f"(acc[mi][ni][2]), "+f"(acc[mi][ni][3])
                        : "r"(a[mi][0]), "r"(a[mi][1]), "r"(a[mi][2]), "r"(a[mi][3]),
                          "r"(b[ni][0]), "r"(b[ni][1]));
        }
        __syncthreads();
    }

    // Epilogue: add bias, split into (hi, lo) bf16 planes.
    const int lr = lane >> 2;
    const int lc = (lane & 3) << 1;
#pragma unroll
    for (int mi = 0; mi < 2; mi++) {
#pragma unroll
        for (int ni = 0; ni < 8; ni++) {
            const int col = bn + wc * 64 + ni * 8 + lc;
            const float b0v = bias[col];
            const float b1v = bias[col + 1];
#pragma unroll
            for (int h = 0; h < 2; h++) {
                const int row = bm + wr * 32 + mi * 16 + lr + h * 8;
                const float x0 = acc[mi][ni][2 * h + 0] + b0v;
                const float x1 = acc[mi][ni][2 * h + 1] + b1v;
                __nv_bfloat16 h0, l0, h1, l1;
                split2(x0, h0, l0);
                split2(x1, h1, l1);
                const size_t off = (size_t)row * L_DIM + col;
                *reinterpret_cast<__nv_bfloat162*>(Ohi + off) = __halves2bfloat162(h0, h1);
                *reinterpret_cast<__nv_bfloat162*>(Olo + off) = __halves2bfloat162(l0, l1);
            }
        }
    }
}

// ---------------------------------------------------------------------------
// One Householder reflection per row: z' = z - 2 v (v.z)/(v.v)
// v reconstructed as hi+lo (error ~2^-18 rel). One block per row.
// ---------------------------------------------------------------------------
__global__ __launch_bounds__(256)
void reflect_kernel(const __nv_bfloat16* __restrict__ vhi,
                    const __nv_bfloat16* __restrict__ vlo,
                    const float* __restrict__ zin,
                    float* __restrict__ zout) {
    const int row = blockIdx.x;
    const int tid = threadIdx.x;
    const size_t base = (size_t)row * L_DIM;

    float v[8], z[8];
    float svz = 0.f, svv = 0.f;
#pragma unroll
    for (int i = 0; i < 8; i++) {
        const int c = tid + i * 256;
        const float vv = __bfloat162float(vhi[base + c]) + __bfloat162float(vlo[base + c]);
        const float zz = zin[base + c];
        v[i] = vv; z[i] = zz;
        svz += vv * zz;
        svv += vv * vv;
    }
#pragma unroll
    for (int o = 16; o > 0; o >>= 1) {
        svz += __shfl_xor_sync(0xFFFFFFFFu, svz, o);
        svv += __shfl_xor_sync(0xFFFFFFFFu, svv, o);
    }
    __shared__ float s[2][8];
    if ((tid & 31) == 0) {
        s[0][tid >> 5] = svz;
        s[1][tid >> 5] = svv;
    }
    __syncthreads();
    float tvz = 0.f, tvv = 0.f;
#pragma unroll
    for (int w = 0; w < 8; w++) { tvz += s[0][w]; tvv += s[1][w]; }
    const float scale = 2.f * tvz / tvv;
#pragma unroll
    for (int i = 0; i < 8; i++) {
        const int c = tid + i * 256;
        zout[base + c] = z[i] - scale * v[i];
    }
}

// ---------------------------------------------------------------------------
extern "C" void kernel_launch(void* const* d_in, const int* in_sizes, int n_in,
                              void* d_out, int out_size) {
    const float* z_in   = (const float*)d_in[0];   // [B, L]
    const float* h_last = (const float*)d_in[1];   // [B, H]
    const float* W0     = (const float*)d_in[2];   // [L, H]
    const float* b0     = (const float*)d_in[3];   // [L]
    const float* Ws     = (const float*)d_in[4];   // [NF-1, L, L]
    const float* bs     = (const float*)d_in[5];   // [NF-1, L]
    float* out          = (float*)d_out;           // [B, L]

    __nv_bfloat16 *Whi, *Wlo, *Ahi, *Alo;
    float* zb;
    cudaGetSymbolAddress((void**)&Whi, g_Whi);
    cudaGetSymbolAddress((void**)&Wlo, g_Wlo);
    cudaGetSymbolAddress((void**)&Ahi, g_Ahi);
    cudaGetSymbolAddress((void**)&Alo, g_Alo);
    cudaGetSymbolAddress((void**)&zb,  g_z);

    const size_t WL = (size_t)L_DIM * L_DIM;        // weight plane elems
    const size_t PL = (size_t)B_DIM * L_DIM;        // activation plane elems

    // Split weights and h_last into bf16 hi/lo planes.
    {
        const int n4w0 = (int)(WL / 4);
        convert_split_kernel<<<(n4w0 + 255) / 256, 256>>>(
            (const float4*)W0, Whi, Wlo, n4w0);
        const int n4ws = (int)(7 * WL / 4);
        convert_split_kernel<<<(n4ws + 255) / 256, 256>>>(
            (const float4*)Ws, Whi + WL, Wlo + WL, n4ws);
        const int n4h = (int)(PL / 4);
        convert_split_kernel<<<(n4h + 255) / 256, 256>>>(
            (const float4*)h_last, Ahi, Alo, n4h);
    }

    dim3 gg(L_DIM / BN, B_DIM / BM);   // (16, 64)
    const float* zcur = z_in;
    int ping = 0;
    for (int j = 0; j < NFLOW; j++) {
        const __nv_bfloat16* ahi = Ahi + (size_t)ping * PL;
        const __nv_bfloat16* alo = Alo + (size_t)ping * PL;
        __nv_bfloat16* ohi = Ahi + (size_t)(ping ^ 1) * PL;
        __nv_bfloat16* olo = Alo + (size_t)(ping ^ 1) * PL;
        const float* bias = (j == 0) ? b0 : (bs + (size_t)(j - 1) * L_DIM);

        gemm_split_kernel<<<gg, 256>>>(ahi, alo,
                                       Whi + (size_t)j * WL, Wlo + (size_t)j * WL,
                                       bias, ohi, olo);

        float* zo = (j == NFLOW - 1) ? out : zb;
        reflect_kernel<<<B_DIM, 256>>>(ohi, olo, zcur, zo);

        zcur = zb;
        ping ^= 1;
    }
}

// round 11
// speedup vs baseline: 1.0860x; 1.0860x over previous
#include <cuda_runtime.h>
#include <cuda_bf16.h>
#include <cstdint>
#include <cstddef>

// ---------------------------------------------------------------------------
// HouseholderFlow via mma.sync (HMMA) — the harness targets compute_103
// (no 'a' feature), so tcgen05 is unavailable; optimize the legacy path.
//   v0 = h_last @ W0^T + b0 ; z = HF(v0, z) ; then 7 more (Ws[j], bs[j]).
// GEMMs: bf16 3-term split (hi*hi + hi*lo + lo*hi), fp32 accumulate.
// K-space fused: 3 regions of 2048 -> one K=6144 chain per output tile.
// ---------------------------------------------------------------------------

#define B_DIM 8192
#define L_DIM 2048
#define NFLOW 8

#define BM 128
#define BN 128
#define BK 64                         // 64 bf16 = 128B rows (SW128 atom)
#define STAGES 3
#define TILES (3 * (L_DIM / BK))      // 96
#define A_BYTES (BM * 128)            // 16384
#define B_BYTES (BN * 128)            // 16384
#define STAGE_BYTES (A_BYTES + B_BYTES)
#define SMEM_REQ (1024 + STAGES * STAGE_BYTES)

// ---- device scratch (allocation-free rule: static __device__ arrays) ----
__device__ __nv_bfloat16 g_Whi[(size_t)NFLOW * L_DIM * L_DIM];
__device__ __nv_bfloat16 g_Wlo[(size_t)NFLOW * L_DIM * L_DIM];
__device__ __nv_bfloat16 g_Ahi[2ull * B_DIM * L_DIM];
__device__ __nv_bfloat16 g_Alo[2ull * B_DIM * L_DIM];
__device__ float         g_z[(size_t)B_DIM * L_DIM];

// ---------------------------------------------------------------------------
__device__ __forceinline__ void split2(float x, __nv_bfloat16& h, __nv_bfloat16& l) {
    h = __float2bfloat16_rn(x);
    l = __float2bfloat16_rn(x - __bfloat162float(h));
}

__global__ void convert_split_kernel(const float4* __restrict__ src,
                                     __nv_bfloat16* __restrict__ hi,
                                     __nv_bfloat16* __restrict__ lo,
                                     int n4) {
    int i = blockIdx.x * blockDim.x + threadIdx.x;
    if (i >= n4) return;
    float4 x = src[i];
    __nv_bfloat16 h0, h1, h2, h3, l0, l1, l2, l3;
    split2(x.x, h0, l0); split2(x.y, h1, l1);
    split2(x.z, h2, l2); split2(x.w, h3, l3);
    __nv_bfloat162* H = reinterpret_cast<__nv_bfloat162*>(hi) + 2 * (size_t)i;
    __nv_bfloat162* L = reinterpret_cast<__nv_bfloat162*>(lo) + 2 * (size_t)i;
    H[0] = __halves2bfloat162(h0, h1);
    H[1] = __halves2bfloat162(h2, h3);
    L[0] = __halves2bfloat162(l0, l1);
    L[1] = __halves2bfloat162(l2, l3);
}

// SW128 swizzle on byte offsets (128B rows): chunk bits [4:6] ^= row bits [0:2]
__device__ __forceinline__ uint32_t sw128(uint32_t off) {
    return off ^ ((off >> 3) & 0x70);
}

// ---------------------------------------------------------------------------
// C[m,n] = sum_k A[m,k] * W[n,k] + bias[n]  (NT), K fused over 3 bf16 planes.
// 256 threads, warp grid 4x2, warp tile 32x64. 3-stage cp.async pipeline,
// register double-buffered ldmatrix fragments.
// ---------------------------------------------------------------------------
__global__ __launch_bounds__(256, 1)
void gemm_hmma_kernel(const __nv_bfloat16* __restrict__ Ahi,
                      const __nv_bfloat16* __restrict__ Alo,
                      const __nv_bfloat16* __restrict__ Whi,
                      const __nv_bfloat16* __restrict__ Wlo,
                      const float* __restrict__ bias,
                      __nv_bfloat16* __restrict__ Ohi,
                      __nv_bfloat16* __restrict__ Olo) {
    extern __shared__ char smem[];
    const uint32_t sbase = (uint32_t)__cvta_generic_to_shared(smem);
    const uint32_t tile0 = (sbase + 1023u) & ~1023u;

    const int tid  = threadIdx.x;
    const int lane = tid & 31;
    const int warp = tid >> 5;
    const int wr   = warp >> 1;     // 0..3, 32 rows each
    const int wc   = warp & 1;      // 0..1, 64 cols each
    const int bm = blockIdx.y * BM;
    const int bn = blockIdx.x * BN;

    float acc[2][8][4];
#pragma unroll
    for (int mi = 0; mi < 2; mi++)
#pragma unroll
        for (int ni = 0; ni < 8; ni++)
#pragma unroll
            for (int e = 0; e < 4; e++) acc[mi][ni][e] = 0.f;

    auto load_tile = [&](int t) {
        const int s  = t % STAGES;
        const int r  = t >> 5;                 // 0=(Ahi,Whi) 1=(Ahi,Wlo) 2=(Alo,Whi)
        const int kk = (t & 31) << 6;          // k elem offset within region
        const __nv_bfloat16* Ap = (r < 2) ? Ahi : Alo;
        const __nv_bfloat16* Bp = (r == 1) ? Wlo : Whi;
        const uint32_t Ab = tile0 + s * STAGE_BYTES;
        const uint32_t Bb = Ab + A_BYTES;
#pragma unroll
        for (int i = 0; i < 4; i++) {          // A: 1024 x 16B chunks
            const int chunk = tid + i * 256;
            const int row = chunk >> 3;
            const int cb  = (chunk & 7) << 4;
            const uint32_t sw = sw128((uint32_t)(row * 128 + cb));
            const void* src = Ap + (size_t)(bm + row) * L_DIM + kk + (cb >> 1);
            asm volatile("cp.async.cg.shared.global [%0], [%1], 16;\n"
                         :: "r"(Ab + sw), "l"(src) : "memory");
        }
#pragma unroll
        for (int i = 0; i < 4; i++) {          // B: 1024 x 16B chunks
            const int chunk = tid + i * 256;
            const int row = chunk >> 3;
            const int cb  = (chunk & 7) << 4;
            const uint32_t sw = sw128((uint32_t)(row * 128 + cb));
            const void* src = Bp + (size_t)(bn + row) * L_DIM + kk + (cb >> 1);
            asm volatile("cp.async.cg.shared.global [%0], [%1], 16;\n"
                         :: "r"(Bb + sw), "l"(src) : "memory");
        }
        asm volatile("cp.async.commit_group;\n" ::: "memory");
    };

    // Per-warp fragment loads (ks = 0..3 selects 16-col sub-block of stage)
    const int arow = wr * 32 + (lane & 15);
    const int akb  = (lane >> 4) << 4;              // 0 or 16 bytes
    const int nrow = wc * 64 + ((lane >> 4) << 3) + (lane & 7);
    const int bkb  = ((lane >> 3) & 1) << 4;        // 0 or 16 bytes

    auto load_afrag = [&](uint32_t Ab, int ks, uint32_t a[2][4]) {
#pragma unroll
        for (int mi = 0; mi < 2; mi++) {
            const uint32_t off = (uint32_t)((arow + mi * 16) * 128 + ks * 32 + akb);
            const uint32_t addr = Ab + sw128(off);
            asm volatile(
                "ldmatrix.sync.aligned.m8n8.x4.shared.b16 {%0,%1,%2,%3}, [%4];"
                : "=r"(a[mi][0]), "=r"(a[mi][1]), "=r"(a[mi][2]), "=r"(a[mi][3])
                : "r"(addr));
        }
    };
    auto load_bfrag = [&](uint32_t Bb, int ks, uint32_t b[8][2]) {
#pragma unroll
        for (int nt = 0; nt < 4; nt++) {
            const uint32_t off = (uint32_t)((nrow + nt * 16) * 128 + ks * 32 + bkb);
            const uint32_t addr = Bb + sw128(off);
            asm volatile(
                "ldmatrix.sync.aligned.m8n8.x4.shared.b16 {%0,%1,%2,%3}, [%4];"
                : "=r"(b[2 * nt][0]), "=r"(b[2 * nt][1]),
                  "=r"(b[2 * nt + 1][0]), "=r"(b[2 * nt + 1][1])
                : "r"(addr));
        }
    };

    // Prologue: stages 0,1 in flight
    load_tile(0);
    load_tile(1);

    uint32_t afr[2][2][4], bfr[2][8][2];

    for (int t = 0; t < TILES; t++) {
        // Issue loads for t+2 (stage (t+2)%3 == (t-1)%3, freed by last sync),
        // then wait for group t and make stage visible.
        if (t + 2 < TILES) {
            load_tile(t + 2);
            asm volatile("cp.async.wait_group 2;\n" ::: "memory");
        } else if (t + 1 < TILES) {
            asm volatile("cp.async.wait_group 1;\n" ::: "memory");
        } else {
            asm volatile("cp.async.wait_group 0;\n" ::: "memory");
        }
        __syncthreads();

        const int s = t % STAGES;
        const uint32_t Ab = tile0 + s * STAGE_BYTES;
        const uint32_t Bb = Ab + A_BYTES;

        load_afrag(Ab, 0, afr[0]);
        load_bfrag(Bb, 0, bfr[0]);
#pragma unroll
        for (int ks = 0; ks < 4; ks++) {
            const int cur = ks & 1;
            if (ks < 3) {
                load_afrag(Ab, ks + 1, afr[cur ^ 1]);
                load_bfrag(Bb, ks + 1, bfr[cur ^ 1]);
            }
#pragma unroll
            for (int mi = 0; mi < 2; mi++)
#pragma unroll
                for (int ni = 0; ni < 8; ni++)
                    asm volatile(
                        "mma.sync.aligned.m16n8k16.row.col.f32.bf16.bf16.f32 "
                        "{%0,%1,%2,%3}, {%4,%5,%6,%7}, {%8,%9}, {%0,%1,%2,%3};"
                        : "+f"(acc[mi][ni][0]), "+f"(acc[mi][ni][1]),
                          "+f"(acc[mi][ni][2]), "+f"(acc[mi][ni][3])
                        : "r"(afr[cur][mi][0]), "r"(afr[cur][mi][1]),
                          "r"(afr[cur][mi][2]), "r"(afr[cur][mi][3]),
                          "r"(bfr[cur][ni][0]), "r"(bfr[cur][ni][1]));
        }
        __syncthreads();   // stage s reusable by the t+3 loads next iteration
    }

    // Epilogue: add bias, split into (hi, lo) bf16 planes.
    const int lr = lane >> 2;
    const int lc = (lane & 3) << 1;
#pragma unroll
    for (int mi = 0; mi < 2; mi++) {
#pragma unroll
        for (int ni = 0; ni < 8; ni++) {
            const int col = bn + wc * 64 + ni * 8 + lc;
            const float b0v = bias[col];
            const float b1v = bias[col + 1];
#pragma unroll
            for (int h = 0; h < 2; h++) {
                const int row = bm + wr * 32 + mi * 16 + lr + h * 8;
                const float x0 = acc[mi][ni][2 * h + 0] + b0v;
                const float x1 = acc[mi][ni][2 * h + 1] + b1v;
                __nv_bfloat16 h0, l0, h1, l1;
                split2(x0, h0, l0);
                split2(x1, h1, l1);
                const size_t off = (size_t)row * L_DIM + col;
                *reinterpret_cast<__nv_bfloat162*>(Ohi + off) = __halves2bfloat162(h0, h1);
                *reinterpret_cast<__nv_bfloat162*>(Olo + off) = __halves2bfloat162(l0, l1);
            }
        }
    }
}

// ---------------------------------------------------------------------------
// Householder reflection per row: z' = z - 2 v (v.z)/(v.v), v = hi + lo.
// ---------------------------------------------------------------------------
__global__ __launch_bounds__(256)
void reflect_kernel(const __nv_bfloat16* __restrict__ vhi,
                    const __nv_bfloat16* __restrict__ vlo,
                    const float* __restrict__ zin,
                    float* __restrict__ zout) {
    const int row = blockIdx.x;
    const int tid = threadIdx.x;
    const size_t base = (size_t)row * L_DIM;

    float v[8], z[8];
    float svz = 0.f, svv = 0.f;
#pragma unroll
    for (int i = 0; i < 8; i++) {
        const int c = tid + i * 256;
        const float vv = __bfloat162float(vhi[base + c]) + __bfloat162float(vlo[base + c]);
        const float zz = zin[base + c];
        v[i] = vv; z[i] = zz;
        svz += vv * zz;
        svv += vv * vv;
    }
#pragma unroll
    for (int o = 16; o > 0; o >>= 1) {
        svz += __shfl_xor_sync(0xFFFFFFFFu, svz, o);
        svv += __shfl_xor_sync(0xFFFFFFFFu, svv, o);
    }
    __shared__ float s[2][8];
    if ((tid & 31) == 0) {
        s[0][tid >> 5] = svz;
        s[1][tid >> 5] = svv;
    }
    __syncthreads();
    float tvz = 0.f, tvv = 0.f;
#pragma unroll
    for (int w = 0; w < 8; w++) { tvz += s[0][w]; tvv += s[1][w]; }
    const float scale = 2.f * tvz / tvv;
#pragma unroll
    for (int i = 0; i < 8; i++) {
        const int c = tid + i * 256;
        zout[base + c] = z[i] - scale * v[i];
    }
}

// ---------------------------------------------------------------------------
extern "C" void kernel_launch(void* const* d_in, const int* in_sizes, int n_in,
                              void* d_out, int out_size) {
    const float* z_in   = (const float*)d_in[0];   // [B, L]
    const float* h_last = (const float*)d_in[1];   // [B, H]
    const float* W0     = (const float*)d_in[2];   // [L, H]
    const float* b0     = (const float*)d_in[3];   // [L]
    const float* Ws     = (const float*)d_in[4];   // [NF-1, L, L]
    const float* bs     = (const float*)d_in[5];   // [NF-1, L]
    float* out          = (float*)d_out;           // [B, L]

    __nv_bfloat16 *Whi, *Wlo, *Ahi, *Alo;
    float* zb;
    cudaGetSymbolAddress((void**)&Whi, g_Whi);
    cudaGetSymbolAddress((void**)&Wlo, g_Wlo);
    cudaGetSymbolAddress((void**)&Ahi, g_Ahi);
    cudaGetSymbolAddress((void**)&Alo, g_Alo);
    cudaGetSymbolAddress((void**)&zb,  g_z);

    cudaFuncSetAttribute(gemm_hmma_kernel,
                         cudaFuncAttributeMaxDynamicSharedMemorySize, SMEM_REQ);

    const size_t WL = (size_t)L_DIM * L_DIM;
    const size_t PL = (size_t)B_DIM * L_DIM;

    // Split weights and h_last into bf16 hi/lo planes.
    {
        const int n4w0 = (int)(WL / 4);
        convert_split_kernel<<<(n4w0 + 255) / 256, 256>>>(
            (const float4*)W0, Whi, Wlo, n4w0);
        const int n4ws = (int)(7 * WL / 4);
        convert_split_kernel<<<(n4ws + 255) / 256, 256>>>(
            (const float4*)Ws, Whi + WL, Wlo + WL, n4ws);
        const int n4h = (int)(PL / 4);
        convert_split_kernel<<<(n4h + 255) / 256, 256>>>(
            (const float4*)h_last, Ahi, Alo, n4h);
    }

    dim3 gg(L_DIM / BN, B_DIM / BM);   // (16, 64)
    const float* zcur = z_in;
    int ping = 0;
    for (int j = 0; j < NFLOW; j++) {
        const __nv_bfloat16* ahi = Ahi + (size_t)ping * PL;
        const __nv_bfloat16* alo = Alo + (size_t)ping * PL;
        __nv_bfloat16* ohi = Ahi + (size_t)(ping ^ 1) * PL;
        __nv_bfloat16* olo = Alo + (size_t)(ping ^ 1) * PL;
        const float* bias = (j == 0) ? b0 : (bs + (size_t)(j - 1) * L_DIM);

        gemm_hmma_kernel<<<gg, 256, SMEM_REQ>>>(ahi, alo,
                                                Whi + (size_t)j * WL,
                                                Wlo + (size_t)j * WL,
                                                bias, ohi, olo);

        float* zo = (j == NFLOW - 1) ? out : zb;
        reflect_kernel<<<B_DIM, 256>>>(ohi, olo, zcur, zo);

        zcur = zb;
        ping ^= 1;
    }
}